// round 3
// baseline (speedup 1.0000x reference)
#include <cuda_runtime.h>
#include <math.h>
#include <stdint.h>

// Problem constants
#define Bsz 4
#define Tsz 2048
#define Csz 1024
#define Hsz 16
#define Dsz 64
#define BH  (Bsz*Hsz)          // 64
#define Msz (Bsz*Tsz)          // 8192

// Scratch (static device globals -- no allocation allowed)
__device__ float g_q[Bsz*Hsz*Tsz*Dsz];   // [B,H,T,D]
__device__ float g_k[Bsz*Hsz*Tsz*Dsz];
__device__ float g_v[Bsz*Hsz*Tsz*Dsz];
__device__ float g_y[Bsz*Tsz*Csz];       // attention output, [B,T,C]
__device__ float g_cs[2 * Tsz * 32];     // cos table [t*32+p], sin at +Tsz*32

// ---------------------------------------------------------------------------
// RoPE cos/sin table, computed in double precision (graph-capturable, cheap).
// ---------------------------------------------------------------------------
__global__ void rope_table_kernel()
{
    int gid = blockIdx.x * blockDim.x + threadIdx.x;   // 0 .. Tsz*32-1
    if (gid >= Tsz * 32) return;
    int t = gid >> 5, p = gid & 31;
    double alpha = pow(10000.0, -(double)p / 32.0);
    double ang = (double)t * alpha;
    g_cs[gid]            = (float)cos(ang);
    g_cs[Tsz * 32 + gid] = (float)sin(ang);
}

// ---------------------------------------------------------------------------
// SGEMM: out = A(MxK) @ W(NxK)^T + bias
// LAYOUT 0: out[m*N + n]  (plain row-major, final projection)
// LAYOUT 1: out[((b*H + h)*T + t)*D + d], m=(b,t), n=(h,d)  (QKV heads),
//           optionally applying RoPE in the epilogue (ROPE=1 for q,k).
// BM=BN=128, BK=16, 256 threads, 8x8 per-thread microtile.
// ---------------------------------------------------------------------------
template<int LAYOUT, int ROPE>
__global__ __launch_bounds__(256, 2) void sgemm_kernel(
    const float* __restrict__ A, const float* __restrict__ W,
    const float* __restrict__ bias, float* __restrict__ out)
{
    const int N = Csz, K = Csz;
    const int BM = 128, BK = 16;

    __shared__ float As[BK][BM + 4];
    __shared__ float Bs[BK][BM + 4];

    int tid = threadIdx.x;
    int m0 = blockIdx.y * BM;
    int n0 = blockIdx.x * BM;

    int lr = tid >> 2;          // 0..63
    int lc = (tid & 3) << 2;    // 0,4,8,12
    int tx = tid & 15;
    int ty = tid >> 4;

    float acc[8][8];
#pragma unroll
    for (int i = 0; i < 8; i++)
#pragma unroll
        for (int j = 0; j < 8; j++) acc[i][j] = 0.f;

    for (int k0 = 0; k0 < K; k0 += BK) {
#pragma unroll
        for (int h = 0; h < 2; ++h) {
            int r = lr + h * 64;
            float4 va = *reinterpret_cast<const float4*>(
                &A[(size_t)(m0 + r) * K + k0 + lc]);
            As[lc + 0][r] = va.x; As[lc + 1][r] = va.y;
            As[lc + 2][r] = va.z; As[lc + 3][r] = va.w;
            float4 vb = *reinterpret_cast<const float4*>(
                &W[(size_t)(n0 + r) * K + k0 + lc]);
            Bs[lc + 0][r] = vb.x; Bs[lc + 1][r] = vb.y;
            Bs[lc + 2][r] = vb.z; Bs[lc + 3][r] = vb.w;
        }
        __syncthreads();

#pragma unroll
        for (int k = 0; k < BK; k++) {
            float a[8], b[8];
            *reinterpret_cast<float4*>(a)     = *reinterpret_cast<float4*>(&As[k][ty * 8]);
            *reinterpret_cast<float4*>(a + 4) = *reinterpret_cast<float4*>(&As[k][ty * 8 + 4]);
            *reinterpret_cast<float4*>(b)     = *reinterpret_cast<float4*>(&Bs[k][tx * 8]);
            *reinterpret_cast<float4*>(b + 4) = *reinterpret_cast<float4*>(&Bs[k][tx * 8 + 4]);
#pragma unroll
            for (int i = 0; i < 8; i++)
#pragma unroll
                for (int j = 0; j < 8; j++)
                    acc[i][j] += a[i] * b[j];
        }
        __syncthreads();
    }

    if (LAYOUT == 0) {
#pragma unroll
        for (int i = 0; i < 8; i++) {
            int m = m0 + ty * 8 + i;
#pragma unroll
            for (int j = 0; j < 8; j++) {
                int n = n0 + tx * 8 + j;
                out[(size_t)m * N + n] = acc[i][j] + bias[n];
            }
        }
        return;
    }

    // LAYOUT 1: heads layout [B,H,T,D]. For RoPE the partner element (d ^ 32,
    // same head/row) is owned by lane^4 at the same (i, j): cols differ by 32
    // = 4 tx-steps of 8; head index n>>6 is unchanged by flipping bit 5.
#pragma unroll
    for (int i = 0; i < 8; i++) {
        int m = m0 + ty * 8 + i;
        int b = m >> 11;            // m / T
        int t = m & (Tsz - 1);
#pragma unroll
        for (int j = 0; j < 8; j++) {
            int n = n0 + tx * 8 + j;
            float v = acc[i][j] + bias[n];
            int h = n >> 6;             // n / D
            int d = n & (Dsz - 1);
            if (ROPE == 0) {
                out[(((size_t)b * Hsz + h) * Tsz + t) * Dsz + d] = v;
            } else {
                int p = d & 31;
                float c = __ldg(&g_cs[t * 32 + p]);
                float s = __ldg(&g_cs[Tsz * 32 + t * 32 + p]);
                float partner = __shfl_xor_sync(0xffffffffu, v, 4);
                float r;
                if (d < 32) r = v * c - partner * s;   // xr' = xr*c - xi*s
                else        r = partner * s + v * c;   // xi' = xr*s + xi*c
                out[(((size_t)b * Hsz + h) * Tsz + t) * Dsz + d] = r;
            }
        }
    }
}

// ---------------------------------------------------------------------------
// Causal flash attention, fp32. Tiles: 64 q-rows x 64 k-rows, D=64.
// 256 threads as 16x16; each thread owns a 4x4 S/P/O microtile.
// Writes directly to [B,T,C] layout for the output projection.
// ---------------------------------------------------------------------------
#define PAD 65
__global__ __launch_bounds__(256) void attn_kernel(
    const float* __restrict__ Q, const float* __restrict__ K,
    const float* __restrict__ V, float* __restrict__ Y)
{
    extern __shared__ float sm[];
    float* Qs = sm;                 // [64][PAD]
    float* Ks = Qs + 64 * PAD;
    float* Vs = Ks + 64 * PAD;
    float* Ps = Vs + 64 * PAD;

    int bh = blockIdx.y;            // 0..63
    int qb = blockIdx.x;            // 0..31
    int tid = threadIdx.x;
    int tx = tid & 15, ty = tid >> 4;

    const float* Qp = Q + ((size_t)bh * Tsz + (size_t)qb * 64) * Dsz;
    const float* Kp = K + (size_t)bh * Tsz * Dsz;
    const float* Vp = V + (size_t)bh * Tsz * Dsz;

    // Load Q tile (64x64)
    for (int idx = tid; idx < 64 * 16; idx += 256) {
        int r = idx >> 4, c4 = (idx & 15) << 2;
        float4 v = *reinterpret_cast<const float4*>(&Qp[(size_t)r * Dsz + c4]);
        Qs[r * PAD + c4 + 0] = v.x; Qs[r * PAD + c4 + 1] = v.y;
        Qs[r * PAD + c4 + 2] = v.z; Qs[r * PAD + c4 + 3] = v.w;
    }

    float o[4][4];
    float mrow[4], lrow[4];
#pragma unroll
    for (int i = 0; i < 4; i++) {
        mrow[i] = -INFINITY; lrow[i] = 0.f;
#pragma unroll
        for (int j = 0; j < 4; j++) o[i][j] = 0.f;
    }

    for (int kb = 0; kb <= qb; ++kb) {
        __syncthreads();   // previous iteration's reads of Ks/Vs/Ps complete
        for (int idx = tid; idx < 64 * 16; idx += 256) {
            int r = idx >> 4, c4 = (idx & 15) << 2;
            size_t g = ((size_t)kb * 64 + r) * Dsz + c4;
            float4 vk = *reinterpret_cast<const float4*>(&Kp[g]);
            Ks[r * PAD + c4 + 0] = vk.x; Ks[r * PAD + c4 + 1] = vk.y;
            Ks[r * PAD + c4 + 2] = vk.z; Ks[r * PAD + c4 + 3] = vk.w;
            float4 vv = *reinterpret_cast<const float4*>(&Vp[g]);
            Vs[r * PAD + c4 + 0] = vv.x; Vs[r * PAD + c4 + 1] = vv.y;
            Vs[r * PAD + c4 + 2] = vv.z; Vs[r * PAD + c4 + 3] = vv.w;
        }
        __syncthreads();

        // S = Q @ K^T  (4x4 per thread)
        float s[4][4];
#pragma unroll
        for (int i = 0; i < 4; i++)
#pragma unroll
            for (int j = 0; j < 4; j++) s[i][j] = 0.f;

#pragma unroll 8
        for (int k = 0; k < 64; k++) {
            float a[4], b[4];
#pragma unroll
            for (int i = 0; i < 4; i++) a[i] = Qs[(ty * 4 + i) * PAD + k];
#pragma unroll
            for (int j = 0; j < 4; j++) b[j] = Ks[(tx * 4 + j) * PAD + k];
#pragma unroll
            for (int i = 0; i < 4; i++)
#pragma unroll
                for (int j = 0; j < 4; j++) s[i][j] += a[i] * b[j];
        }

        const float scale = 0.125f;   // 1/sqrt(64)
#pragma unroll
        for (int i = 0; i < 4; i++)
#pragma unroll
            for (int j = 0; j < 4; j++) s[i][j] *= scale;

        if (kb == qb) {
#pragma unroll
            for (int i = 0; i < 4; i++)
#pragma unroll
                for (int j = 0; j < 4; j++)
                    if (tx * 4 + j > ty * 4 + i) s[i][j] = -INFINITY;
        }

        // online softmax per row (16 threads share a row; shfl over 16 lanes)
#pragma unroll
        for (int i = 0; i < 4; i++) {
            float mt = s[i][0];
#pragma unroll
            for (int j = 1; j < 4; j++) mt = fmaxf(mt, s[i][j]);
#pragma unroll
            for (int off = 8; off > 0; off >>= 1)
                mt = fmaxf(mt, __shfl_xor_sync(0xffffffffu, mt, off));
            float mnew = fmaxf(mrow[i], mt);
            float corr = __expf(mrow[i] - mnew);
            float lt = 0.f;
#pragma unroll
            for (int j = 0; j < 4; j++) {
                float p = __expf(s[i][j] - mnew);
                s[i][j] = p;
                lt += p;
            }
#pragma unroll
            for (int off = 8; off > 0; off >>= 1)
                lt += __shfl_xor_sync(0xffffffffu, lt, off);
            lrow[i] = lrow[i] * corr + lt;
            mrow[i] = mnew;
#pragma unroll
            for (int j = 0; j < 4; j++) o[i][j] *= corr;
        }

        // stage P into smem
#pragma unroll
        for (int i = 0; i < 4; i++)
#pragma unroll
            for (int j = 0; j < 4; j++)
                Ps[(ty * 4 + i) * PAD + tx * 4 + j] = s[i][j];
        __syncthreads();

        // O += P @ V
#pragma unroll 8
        for (int c = 0; c < 64; c++) {
            float a[4], b[4];
#pragma unroll
            for (int i = 0; i < 4; i++) a[i] = Ps[(ty * 4 + i) * PAD + c];
#pragma unroll
            for (int j = 0; j < 4; j++) b[j] = Vs[c * PAD + tx * 4 + j];
#pragma unroll
            for (int i = 0; i < 4; i++)
#pragma unroll
                for (int j = 0; j < 4; j++) o[i][j] += a[i] * b[j];
        }
    }

    // epilogue: normalize and write to [B,T,C]
    int b = bh >> 4, h = bh & 15;
#pragma unroll
    for (int i = 0; i < 4; i++) {
        int t = qb * 64 + ty * 4 + i;
        float inv_l = 1.f / lrow[i];
#pragma unroll
        for (int j = 0; j < 4; j++) {
            int d = tx * 4 + j;
            Y[((size_t)b * Tsz + t) * Csz + h * Dsz + d] = o[i][j] * inv_l;
        }
    }
}

// ---------------------------------------------------------------------------
// Launch
// ---------------------------------------------------------------------------
extern "C" void kernel_launch(void* const* d_in, const int* in_sizes, int n_in,
                              void* d_out, int out_size)
{
    const float* x  = (const float*)d_in[0];
    const float* wq = (const float*)d_in[1];
    const float* bq = (const float*)d_in[2];
    const float* wk = (const float*)d_in[3];
    const float* bk = (const float*)d_in[4];
    const float* wv = (const float*)d_in[5];
    const float* bv = (const float*)d_in[6];
    const float* wp = (const float*)d_in[7];
    const float* bp = (const float*)d_in[8];
    float* out = (float*)d_out;

    float *q, *k, *v, *y;
    cudaGetSymbolAddress((void**)&q, g_q);
    cudaGetSymbolAddress((void**)&k, g_k);
    cudaGetSymbolAddress((void**)&v, g_v);
    cudaGetSymbolAddress((void**)&y, g_y);

    // RoPE cos/sin table (double-precision build, fp32 store)
    rope_table_kernel<<<(Tsz * 32 + 255) / 256, 256>>>();

    dim3 ggrid(Csz / 128, Msz / 128);   // (8, 64)

    sgemm_kernel<1, 1><<<ggrid, 256>>>(x, wq, bq, q);   // Q proj + RoPE
    sgemm_kernel<1, 1><<<ggrid, 256>>>(x, wk, bk, k);   // K proj + RoPE
    sgemm_kernel<1, 0><<<ggrid, 256>>>(x, wv, bv, v);   // V proj

    int smem = 4 * 64 * PAD * sizeof(float);   // 66,560 B
    cudaFuncSetAttribute(attn_kernel, cudaFuncAttributeMaxDynamicSharedMemorySize, smem);
    attn_kernel<<<dim3(Tsz / 64, BH), 256, smem>>>(q, k, v, y);

    sgemm_kernel<0, 0><<<ggrid, 256>>>(y, wp, bp, out);
}

// round 7
// speedup vs baseline: 2.6296x; 2.6296x over previous
#include <cuda_runtime.h>
#include <cuda_bf16.h>
#include <math.h>
#include <stdint.h>

// Problem constants
#define Bsz 4
#define Tsz 2048
#define Csz 1024
#define Hsz 16
#define Dsz 64
#define BH  (Bsz*Hsz)          // 64
#define Msz (Bsz*Tsz)          // 8192

// ---------------------------------------------------------------------------
// Scratch (static device globals -- no allocation allowed)
// ---------------------------------------------------------------------------
__device__ float g_cs[2 * Tsz * 32];     // cos table [t*32+p], sin at +Tsz*32

// split-bf16 operands
__device__ __nv_bfloat16 g_xhi[Msz*Csz], g_xlo[Msz*Csz];
__device__ __nv_bfloat16 g_yhi[Msz*Csz], g_ylo[Msz*Csz];     // attn out [B,T,C]
__device__ __nv_bfloat16 g_qhi[Msz*Csz], g_qlo[Msz*Csz];     // [B,H,T,D]
__device__ __nv_bfloat16 g_khi[Msz*Csz], g_klo[Msz*Csz];
__device__ __nv_bfloat16 g_vhi[Msz*Csz], g_vlo[Msz*Csz];
__device__ __nv_bfloat16 g_wqhi[Csz*Csz], g_wqlo[Csz*Csz];
__device__ __nv_bfloat16 g_wkhi[Csz*Csz], g_wklo[Csz*Csz];
__device__ __nv_bfloat16 g_wvhi[Csz*Csz], g_wvlo[Csz*Csz];
__device__ __nv_bfloat16 g_wphi[Csz*Csz], g_wplo[Csz*Csz];

// ---------------------------------------------------------------------------
// Warp-level tensor-core primitives (base sm_80+ PTX: valid in compute_103)
// ---------------------------------------------------------------------------
__device__ __forceinline__ uint32_t smem_u32(const void* p) {
    uint32_t a;
    asm("{ .reg .u64 t; cvta.to.shared.u64 t, %1; cvt.u32.u64 %0, t; }"
        : "=r"(a) : "l"(p));
    return a;
}
__device__ __forceinline__ void ldsm_x4(uint32_t* r, uint32_t a) {
    asm volatile("ldmatrix.sync.aligned.m8n8.x4.shared.b16 {%0,%1,%2,%3}, [%4];"
                 : "=r"(r[0]), "=r"(r[1]), "=r"(r[2]), "=r"(r[3]) : "r"(a));
}
__device__ __forceinline__ void ldsm_x2(uint32_t* r, uint32_t a) {
    asm volatile("ldmatrix.sync.aligned.m8n8.x2.shared.b16 {%0,%1}, [%2];"
                 : "=r"(r[0]), "=r"(r[1]) : "r"(a));
}
__device__ __forceinline__ void ldsm_x2t(uint32_t* r, uint32_t a) {
    asm volatile("ldmatrix.sync.aligned.m8n8.x2.trans.shared.b16 {%0,%1}, [%2];"
                 : "=r"(r[0]), "=r"(r[1]) : "r"(a));
}
__device__ __forceinline__ void mma_bf16(float* c, const uint32_t* a, const uint32_t* b) {
    asm volatile("mma.sync.aligned.m16n8k16.row.col.f32.bf16.bf16.f32 "
                 "{%0,%1,%2,%3}, {%4,%5,%6,%7}, {%8,%9}, {%0,%1,%2,%3};"
                 : "+f"(c[0]), "+f"(c[1]), "+f"(c[2]), "+f"(c[3])
                 : "r"(a[0]), "r"(a[1]), "r"(a[2]), "r"(a[3]),
                   "r"(b[0]), "r"(b[1]));
}
#define CP_ASYNC16(s, g) \
    asm volatile("cp.async.cg.shared.global [%0], [%1], 16;" :: "r"(s), "l"(g))
#define CP_COMMIT() asm volatile("cp.async.commit_group;" ::: "memory")
#define CP_WAIT(N)  asm volatile("cp.async.wait_group %0;" :: "n"(N) : "memory")

__device__ __forceinline__ uint32_t packbf(float a, float b) {
    __nv_bfloat162 t = __floats2bfloat162_rn(a, b);   // .x = a (low), .y = b (high)
    return *(uint32_t*)&t;
}

// ---------------------------------------------------------------------------
// RoPE cos/sin table (double precision build)
// ---------------------------------------------------------------------------
__global__ void rope_table_kernel()
{
    int gid = blockIdx.x * blockDim.x + threadIdx.x;
    if (gid >= Tsz * 32) return;
    int t = gid >> 5, p = gid & 31;
    double alpha = pow(10000.0, -(double)p / 32.0);
    double ang = (double)t * alpha;
    g_cs[gid]            = (float)cos(ang);
    g_cs[Tsz * 32 + gid] = (float)sin(ang);
}

// ---------------------------------------------------------------------------
// fp32 -> (bf16 hi, bf16 lo) split conversion
// ---------------------------------------------------------------------------
__global__ void cvt_hilo_kernel(const float* __restrict__ src,
                                __nv_bfloat16* __restrict__ hi,
                                __nv_bfloat16* __restrict__ lo, int n)
{
    int i = blockIdx.x * blockDim.x + threadIdx.x;
    if (i >= n) return;
    float v = src[i];
    __nv_bfloat16 h = __float2bfloat16(v);
    hi[i] = h;
    lo[i] = __float2bfloat16(v - __bfloat162float(h));
}

// ---------------------------------------------------------------------------
// Split-bf16 GEMM via mma.sync: (8192,1024) = A @ W^T + bias
// Block 128x128, BK=32, 8 warps (4m x 2n), warp tile 32x64.
// LAYOUT 0: fp32 out[m*N+n].  LAYOUT 1: bf16 hi/lo out in heads layout
// [B,H,T,D] (+ fused RoPE if ROPE=1).
// ---------------------------------------------------------------------------
#define GSTRIDE 80
#define GTILEB  (128 * GSTRIDE)
#define GSTAGEB (4 * GTILEB)
#define GSMEM   (2 * GSTAGEB)

template<int LAYOUT, int ROPE>
__global__ __launch_bounds__(256) void mma_gemm(
    const __nv_bfloat16* __restrict__ Ahi, const __nv_bfloat16* __restrict__ Alo,
    const __nv_bfloat16* __restrict__ Whi, const __nv_bfloat16* __restrict__ Wlo,
    const float* __restrict__ bias, float* __restrict__ outf,
    __nv_bfloat16* __restrict__ outhi, __nv_bfloat16* __restrict__ outlo)
{
    extern __shared__ char smem[];
    const uint32_t sb = smem_u32(smem);
    const int tid = threadIdx.x, lane = tid & 31, wid = tid >> 5;
    const int mw = wid >> 1, nw = wid & 1;
    const int m0 = blockIdx.y * 128, n0 = blockIdx.x * 128;
    const int K = Csz;

    const char* srcs[4] = {
        (const char*)(Ahi + (size_t)m0 * K), (const char*)(Alo + (size_t)m0 * K),
        (const char*)(Whi + (size_t)n0 * K), (const char*)(Wlo + (size_t)n0 * K) };

    auto load_stage = [&](int s, int k0) {
        uint32_t sbase = sb + s * GSTAGEB;
#pragma unroll
        for (int t = 0; t < 4; ++t) {
#pragma unroll
            for (int c2 = 0; c2 < 2; ++c2) {
                int c = tid + c2 * 256;
                int row = c >> 2, sub = c & 3;
                const char* g = srcs[t] + (size_t)row * (K * 2) + k0 * 2 + sub * 16;
                uint32_t sa = sbase + t * GTILEB + row * GSTRIDE + sub * 16;
                CP_ASYNC16(sa, g);
            }
        }
        CP_COMMIT();
    };

    float acc[2][8][4];
#pragma unroll
    for (int mf = 0; mf < 2; ++mf)
#pragma unroll
        for (int nf = 0; nf < 8; ++nf)
#pragma unroll
            for (int e = 0; e < 4; ++e) acc[mf][nf][e] = 0.f;

    load_stage(0, 0);

    for (int it = 0; it < 32; ++it) {
        const int s = it & 1;
        if (it + 1 < 32) { load_stage(s ^ 1, (it + 1) * 32); CP_WAIT(1); }
        else             { CP_WAIT(0); }
        __syncthreads();

        const uint32_t ah_b = sb + s * GSTAGEB;
        const uint32_t al_b = ah_b + GTILEB;
        const uint32_t bh_b = ah_b + 2 * GTILEB;
        const uint32_t bl_b = ah_b + 3 * GTILEB;

#pragma unroll
        for (int ks = 0; ks < 2; ++ks) {
            uint32_t a_hi[2][4], a_lo[2][4];
            const int acol = (ks * 16 + (lane >> 4) * 8) * 2;
#pragma unroll
            for (int mf = 0; mf < 2; ++mf) {
                int arow = mw * 32 + mf * 16 + (lane & 15);
                ldsm_x4(a_hi[mf], ah_b + arow * GSTRIDE + acol);
                ldsm_x4(a_lo[mf], al_b + arow * GSTRIDE + acol);
            }
            const int bcol = (ks * 16 + ((lane >> 3) & 1) * 8) * 2;
#pragma unroll
            for (int nf = 0; nf < 8; ++nf) {
                uint32_t b_hi[2], b_lo[2];
                int brow = nw * 64 + nf * 8 + (lane & 7);
                ldsm_x2(b_hi, bh_b + brow * GSTRIDE + bcol);
                ldsm_x2(b_lo, bl_b + brow * GSTRIDE + bcol);
#pragma unroll
                for (int mf = 0; mf < 2; ++mf) {
                    mma_bf16(acc[mf][nf], a_hi[mf], b_hi);
                    mma_bf16(acc[mf][nf], a_hi[mf], b_lo);
                    mma_bf16(acc[mf][nf], a_lo[mf], b_hi);
                }
            }
        }
        __syncthreads();
    }

    // ---------------- epilogue ----------------
#pragma unroll
    for (int mf = 0; mf < 2; ++mf) {
#pragma unroll
        for (int half = 0; half < 2; ++half) {
            const int m = m0 + mw * 32 + mf * 16 + (lane >> 2) + half * 8;
            if (LAYOUT == 0) {
#pragma unroll
                for (int nf = 0; nf < 8; ++nf) {
                    int n = n0 + nw * 64 + nf * 8 + (lane & 3) * 2;
                    outf[(size_t)m * Csz + n]     = acc[mf][nf][half * 2 + 0] + __ldg(&bias[n]);
                    outf[(size_t)m * Csz + n + 1] = acc[mf][nf][half * 2 + 1] + __ldg(&bias[n + 1]);
                }
            } else {
                const int b = m >> 11, t = m & (Tsz - 1);
                const int h = (n0 + nw * 64) >> 6;
                const size_t base = (((size_t)b * Hsz + h) * Tsz + t) * Dsz;
                if (ROPE == 0) {
#pragma unroll
                    for (int nf = 0; nf < 8; ++nf) {
                        int d = nf * 8 + (lane & 3) * 2;
                        int n = n0 + nw * 64 + d;
                        float v0 = acc[mf][nf][half * 2 + 0] + __ldg(&bias[n]);
                        float v1 = acc[mf][nf][half * 2 + 1] + __ldg(&bias[n + 1]);
                        __nv_bfloat16 h0 = __float2bfloat16(v0), h1 = __float2bfloat16(v1);
                        *(__nv_bfloat162*)(outhi + base + d) =
                            __floats2bfloat162_rn(v0, v1);  // hi via rn = same as h0,h1
                        *(__nv_bfloat162*)(outlo + base + d) =
                            __floats2bfloat162_rn(v0 - __bfloat162float(h0),
                                                  v1 - __bfloat162float(h1));
                    }
                } else {
                    // pairs (d, d+32): frag nf (d<32) pairs with frag nf+4
#pragma unroll
                    for (int nf = 0; nf < 4; ++nf) {
#pragma unroll
                        for (int e = 0; e < 2; ++e) {
                            int d = nf * 8 + (lane & 3) * 2 + e;
                            int n = n0 + nw * 64 + d;
                            float xr = acc[mf][nf][half * 2 + e]     + __ldg(&bias[n]);
                            float xi = acc[mf][nf + 4][half * 2 + e] + __ldg(&bias[n + 32]);
                            float cth = __ldg(&g_cs[t * 32 + d]);
                            float sth = __ldg(&g_cs[Tsz * 32 + t * 32 + d]);
                            float r0 = xr * cth - xi * sth;
                            float r1 = xr * sth + xi * cth;
                            __nv_bfloat16 h0 = __float2bfloat16(r0);
                            __nv_bfloat16 h1 = __float2bfloat16(r1);
                            outhi[base + d]      = h0;
                            outhi[base + d + 32] = h1;
                            outlo[base + d]      = __float2bfloat16(r0 - __bfloat162float(h0));
                            outlo[base + d + 32] = __float2bfloat16(r1 - __bfloat162float(h1));
                        }
                    }
                }
            }
        }
    }
}

// ---------------------------------------------------------------------------
// Causal flash attention, split-bf16 mma.sync.
// Block: 128 threads (4 warps), 64 q-rows; warp owns 16 rows x all 64 cols.
// K/V tiles (64x64 hi/lo) double-buffered via cp.async.
// Writes y as bf16 hi/lo [B,T,C].
// ---------------------------------------------------------------------------
#define ASTRIDE 144
#define ATILE   (64 * ASTRIDE)          // 9216
#define ASTAGE  (4 * ATILE)             // 36864
#define ASMEM   (2 * ASTAGE)            // 73728

__global__ __launch_bounds__(128) void attn_mma(
    const __nv_bfloat16* __restrict__ Qhi, const __nv_bfloat16* __restrict__ Qlo,
    const __nv_bfloat16* __restrict__ Khi, const __nv_bfloat16* __restrict__ Klo,
    const __nv_bfloat16* __restrict__ Vhi, const __nv_bfloat16* __restrict__ Vlo,
    __nv_bfloat16* __restrict__ Yhi, __nv_bfloat16* __restrict__ Ylo)
{
    extern __shared__ char smem[];
    const uint32_t sb = smem_u32(smem);
    const int tid = threadIdx.x, lane = tid & 31, w = tid >> 5;
    const int bh = blockIdx.y, qb = blockIdx.x;

    // ---- stage Q hi/lo into stage0 tiles 0,1; extract A fragments ----
    {
        const char* s0 = (const char*)(Qhi + ((size_t)bh * Tsz + qb * 64) * Dsz);
        const char* s1 = (const char*)(Qlo + ((size_t)bh * Tsz + qb * 64) * Dsz);
#pragma unroll
        for (int i = 0; i < 4; ++i) {
            int c = tid + i * 128, row = c >> 3, sub = c & 7;
            CP_ASYNC16(sb + 0 * ATILE + row * ASTRIDE + sub * 16, s0 + row * 128 + sub * 16);
            CP_ASYNC16(sb + 1 * ATILE + row * ASTRIDE + sub * 16, s1 + row * 128 + sub * 16);
        }
        CP_COMMIT(); CP_WAIT(0);
        __syncthreads();
    }
    uint32_t qh[4][4], ql[4][4];
    {
        const int arow = w * 16 + (lane & 15);
        const int acoff = (lane >> 4) * 8;
#pragma unroll
        for (int kt = 0; kt < 4; ++kt) {
            ldsm_x4(qh[kt], sb + 0 * ATILE + arow * ASTRIDE + (acoff + kt * 16) * 2);
            ldsm_x4(ql[kt], sb + 1 * ATILE + arow * ASTRIDE + (acoff + kt * 16) * 2);
        }
    }
    __syncthreads();

    const char* kh_p = (const char*)(Khi + (size_t)bh * Tsz * Dsz);
    const char* kl_p = (const char*)(Klo + (size_t)bh * Tsz * Dsz);
    const char* vh_p = (const char*)(Vhi + (size_t)bh * Tsz * Dsz);
    const char* vl_p = (const char*)(Vlo + (size_t)bh * Tsz * Dsz);

    auto load_kv = [&](int st, int kb) {
        uint32_t sbase = sb + st * ASTAGE;
        const char* srcs[4] = { kh_p + (size_t)kb * 64 * 128, kl_p + (size_t)kb * 64 * 128,
                                vh_p + (size_t)kb * 64 * 128, vl_p + (size_t)kb * 64 * 128 };
#pragma unroll
        for (int t = 0; t < 4; ++t)
#pragma unroll
            for (int i = 0; i < 4; ++i) {
                int c = tid + i * 128, row = c >> 3, sub = c & 7;
                CP_ASYNC16(sbase + t * ATILE + row * ASTRIDE + sub * 16,
                           srcs[t] + row * 128 + sub * 16);
            }
        CP_COMMIT();
    };

    float o[8][4];
    float mrow[2] = { -INFINITY, -INFINITY }, lrow[2] = { 0.f, 0.f };
#pragma unroll
    for (int nf = 0; nf < 8; ++nf)
#pragma unroll
        for (int e = 0; e < 4; ++e) o[nf][e] = 0.f;

    load_kv(0, 0);

    for (int kb = 0; kb <= qb; ++kb) {
        const int st = kb & 1;
        if (kb < qb) { load_kv(st ^ 1, kb + 1); CP_WAIT(1); }
        else         { CP_WAIT(0); }
        __syncthreads();

        const uint32_t khb = sb + st * ASTAGE;
        const uint32_t klb = khb + ATILE;
        const uint32_t vhb = khb + 2 * ATILE;
        const uint32_t vlb = khb + 3 * ATILE;

        // ---- S = Q @ K^T (split) ----
        float s[8][4];
#pragma unroll
        for (int nf = 0; nf < 8; ++nf)
#pragma unroll
            for (int e = 0; e < 4; ++e) s[nf][e] = 0.f;

        const int brow_off = (lane & 7) * ASTRIDE;
#pragma unroll
        for (int kt = 0; kt < 4; ++kt) {
            const int bcol = (kt * 16 + ((lane >> 3) & 1) * 8) * 2;
#pragma unroll
            for (int nf = 0; nf < 8; ++nf) {
                uint32_t kbh[2], kbl[2];
                ldsm_x2(kbh, khb + (nf * 8) * ASTRIDE + brow_off + bcol);
                ldsm_x2(kbl, klb + (nf * 8) * ASTRIDE + brow_off + bcol);
                mma_bf16(s[nf], qh[kt], kbh);
                mma_bf16(s[nf], qh[kt], kbl);
                mma_bf16(s[nf], ql[kt], kbh);
            }
        }

        // scale + causal mask
#pragma unroll
        for (int nf = 0; nf < 8; ++nf)
#pragma unroll
            for (int e = 0; e < 4; ++e) s[nf][e] *= 0.125f;
        if (kb == qb) {
#pragma unroll
            for (int nf = 0; nf < 8; ++nf)
#pragma unroll
                for (int e = 0; e < 4; ++e) {
                    int col = nf * 8 + (lane & 3) * 2 + (e & 1);
                    int row = w * 16 + (lane >> 2) + (e >> 1) * 8;
                    if (col > row) s[nf][e] = -INFINITY;
                }
        }

        // ---- online softmax (rows: 4-lane groups; bits 0,1 of lane) ----
#pragma unroll
        for (int half = 0; half < 2; ++half) {
            float mt = -INFINITY;
#pragma unroll
            for (int nf = 0; nf < 8; ++nf) {
                mt = fmaxf(mt, s[nf][half * 2 + 0]);
                mt = fmaxf(mt, s[nf][half * 2 + 1]);
            }
            mt = fmaxf(mt, __shfl_xor_sync(0xffffffffu, mt, 1));
            mt = fmaxf(mt, __shfl_xor_sync(0xffffffffu, mt, 2));
            float mnew = fmaxf(mrow[half], mt);
            float corr = __expf(mrow[half] - mnew);
            float lt = 0.f;
#pragma unroll
            for (int nf = 0; nf < 8; ++nf) {
                float p0 = __expf(s[nf][half * 2 + 0] - mnew);
                float p1 = __expf(s[nf][half * 2 + 1] - mnew);
                s[nf][half * 2 + 0] = p0; s[nf][half * 2 + 1] = p1;
                lt += p0 + p1;
            }
            lt += __shfl_xor_sync(0xffffffffu, lt, 1);
            lt += __shfl_xor_sync(0xffffffffu, lt, 2);
            lrow[half] = lrow[half] * corr + lt;
            mrow[half] = mnew;
#pragma unroll
            for (int nf = 0; nf < 8; ++nf) {
                o[nf][half * 2 + 0] *= corr;
                o[nf][half * 2 + 1] *= corr;
            }
        }

        // ---- O += P @ V (split): P accumulator frags -> A frags in-place ----
#pragma unroll
        for (int kt = 0; kt < 4; ++kt) {
            uint32_t pa_h[4], pa_l[4];
#pragma unroll
            for (int g = 0; g < 2; ++g) {            // g=0 -> a0/a1, g=1 -> a2/a3
                const float* f = s[2 * kt + g];
                __nv_bfloat16 h0 = __float2bfloat16(f[0]), h1 = __float2bfloat16(f[1]);
                __nv_bfloat16 h2 = __float2bfloat16(f[2]), h3 = __float2bfloat16(f[3]);
                pa_h[2 * g + 0] = packbf(f[0], f[1]);
                pa_h[2 * g + 1] = packbf(f[2], f[3]);
                pa_l[2 * g + 0] = packbf(f[0] - __bfloat162float(h0),
                                         f[1] - __bfloat162float(h1));
                pa_l[2 * g + 1] = packbf(f[2] - __bfloat162float(h2),
                                         f[3] - __bfloat162float(h3));
            }
            // reorder: built (a0,a1 from frag 2kt) at [0],[1]; (a2,a3 from 2kt+1) at [2],[3] -- correct
            const int vrow = (kt * 16 + (lane & 15)) * ASTRIDE;
#pragma unroll
            for (int nf = 0; nf < 8; ++nf) {
                uint32_t vbh[2], vbl[2];
                ldsm_x2t(vbh, vhb + vrow + nf * 16);
                ldsm_x2t(vbl, vlb + vrow + nf * 16);
                mma_bf16(o[nf], pa_h, vbh);
                mma_bf16(o[nf], pa_h, vbl);
                mma_bf16(o[nf], pa_l, vbh);
            }
        }
        __syncthreads();
    }

    // ---- epilogue: normalize, split, write [B,T,C] bf16 hi/lo ----
    const int b = bh >> 4, h = bh & 15;
#pragma unroll
    for (int half = 0; half < 2; ++half) {
        const int t = qb * 64 + w * 16 + (lane >> 2) + half * 8;
        const float inv = 1.f / lrow[half];
        const size_t base = ((size_t)b * Tsz + t) * Csz + h * 64;
#pragma unroll
        for (int nf = 0; nf < 8; ++nf) {
            int d = nf * 8 + (lane & 3) * 2;
            float v0 = o[nf][half * 2 + 0] * inv;
            float v1 = o[nf][half * 2 + 1] * inv;
            __nv_bfloat16 h0 = __float2bfloat16(v0), h1 = __float2bfloat16(v1);
            *(__nv_bfloat162*)(Yhi + base + d) = __floats2bfloat162_rn(v0, v1);
            *(__nv_bfloat162*)(Ylo + base + d) =
                __floats2bfloat162_rn(v0 - __bfloat162float(h0),
                                      v1 - __bfloat162float(h1));
        }
    }
}

// ---------------------------------------------------------------------------
// Launch
// ---------------------------------------------------------------------------
extern "C" void kernel_launch(void* const* d_in, const int* in_sizes, int n_in,
                              void* d_out, int out_size)
{
    const float* x  = (const float*)d_in[0];
    const float* wq = (const float*)d_in[1];
    const float* bq = (const float*)d_in[2];
    const float* wk = (const float*)d_in[3];
    const float* bk = (const float*)d_in[4];
    const float* wv = (const float*)d_in[5];
    const float* bv = (const float*)d_in[6];
    const float* wp = (const float*)d_in[7];
    const float* bp = (const float*)d_in[8];
    float* out = (float*)d_out;

    __nv_bfloat16 *xhi, *xlo, *yhi, *ylo;
    __nv_bfloat16 *qhi, *qlo, *khi, *klo, *vhi, *vlo;
    __nv_bfloat16 *wqhi, *wqlo, *wkhi, *wklo, *wvhi, *wvlo, *wphi, *wplo;
    cudaGetSymbolAddress((void**)&xhi, g_xhi);   cudaGetSymbolAddress((void**)&xlo, g_xlo);
    cudaGetSymbolAddress((void**)&yhi, g_yhi);   cudaGetSymbolAddress((void**)&ylo, g_ylo);
    cudaGetSymbolAddress((void**)&qhi, g_qhi);   cudaGetSymbolAddress((void**)&qlo, g_qlo);
    cudaGetSymbolAddress((void**)&khi, g_khi);   cudaGetSymbolAddress((void**)&klo, g_klo);
    cudaGetSymbolAddress((void**)&vhi, g_vhi);   cudaGetSymbolAddress((void**)&vlo, g_vlo);
    cudaGetSymbolAddress((void**)&wqhi, g_wqhi); cudaGetSymbolAddress((void**)&wqlo, g_wqlo);
    cudaGetSymbolAddress((void**)&wkhi, g_wkhi); cudaGetSymbolAddress((void**)&wklo, g_wklo);
    cudaGetSymbolAddress((void**)&wvhi, g_wvhi); cudaGetSymbolAddress((void**)&wvlo, g_wvlo);
    cudaGetSymbolAddress((void**)&wphi, g_wphi); cudaGetSymbolAddress((void**)&wplo, g_wplo);

    rope_table_kernel<<<(Tsz * 32 + 255) / 256, 256>>>();

    const int nx = Msz * Csz, nw = Csz * Csz;
    cvt_hilo_kernel<<<(nx + 255) / 256, 256>>>(x,  xhi,  xlo,  nx);
    cvt_hilo_kernel<<<(nw + 255) / 256, 256>>>(wq, wqhi, wqlo, nw);
    cvt_hilo_kernel<<<(nw + 255) / 256, 256>>>(wk, wkhi, wklo, nw);
    cvt_hilo_kernel<<<(nw + 255) / 256, 256>>>(wv, wvhi, wvlo, nw);
    cvt_hilo_kernel<<<(nw + 255) / 256, 256>>>(wp, wphi, wplo, nw);

    cudaFuncSetAttribute(mma_gemm<1, 1>, cudaFuncAttributeMaxDynamicSharedMemorySize, GSMEM);
    cudaFuncSetAttribute(mma_gemm<1, 0>, cudaFuncAttributeMaxDynamicSharedMemorySize, GSMEM);
    cudaFuncSetAttribute(mma_gemm<0, 0>, cudaFuncAttributeMaxDynamicSharedMemorySize, GSMEM);
    cudaFuncSetAttribute(attn_mma, cudaFuncAttributeMaxDynamicSharedMemorySize, ASMEM);

    dim3 ggrid(Csz / 128, Msz / 128);   // (8, 64)
    mma_gemm<1, 1><<<ggrid, 256, GSMEM>>>(xhi, xlo, wqhi, wqlo, bq, nullptr, qhi, qlo);
    mma_gemm<1, 1><<<ggrid, 256, GSMEM>>>(xhi, xlo, wkhi, wklo, bk, nullptr, khi, klo);
    mma_gemm<1, 0><<<ggrid, 256, GSMEM>>>(xhi, xlo, wvhi, wvlo, bv, nullptr, vhi, vlo);

    attn_mma<<<dim3(Tsz / 64, BH), 128, ASMEM>>>(qhi, qlo, khi, klo, vhi, vlo, yhi, ylo);

    mma_gemm<0, 0><<<ggrid, 256, GSMEM>>>(yhi, ylo, wphi, wplo, bp, out, nullptr, nullptr);
}

// round 9
// speedup vs baseline: 2.6441x; 1.0055x over previous
#include <cuda_runtime.h>
#include <cuda_bf16.h>
#include <math.h>
#include <stdint.h>

// Problem constants
#define Bsz 4
#define Tsz 2048
#define Csz 1024
#define Hsz 16
#define Dsz 64
#define BH  (Bsz*Hsz)          // 64
#define Msz (Bsz*Tsz)          // 8192

// ---------------------------------------------------------------------------
// Scratch (static device globals -- no allocation allowed)
// ---------------------------------------------------------------------------
__device__ float g_cs[2 * Tsz * 32];     // cos table [t*32+p], sin at +Tsz*32
__device__ const float* g_biasp[3];      // q,k,v bias pointers (set by kernel)

__device__ __nv_bfloat16 g_xhi[Msz*Csz], g_xlo[Msz*Csz];
__device__ __nv_bfloat16 g_yhi[Msz*Csz], g_ylo[Msz*Csz];     // attn out [B,T,C]
__device__ __nv_bfloat16 g_qhi[Msz*Csz], g_qlo[Msz*Csz];     // [B,H,T,D]
__device__ __nv_bfloat16 g_khi[Msz*Csz], g_klo[Msz*Csz];
__device__ __nv_bfloat16 g_vhi[Msz*Csz], g_vlo[Msz*Csz];
__device__ __nv_bfloat16 g_wqhi[Csz*Csz], g_wqlo[Csz*Csz];
__device__ __nv_bfloat16 g_wkhi[Csz*Csz], g_wklo[Csz*Csz];
__device__ __nv_bfloat16 g_wvhi[Csz*Csz], g_wvlo[Csz*Csz];
__device__ __nv_bfloat16 g_wphi[Csz*Csz], g_wplo[Csz*Csz];

// ---------------------------------------------------------------------------
// Warp-level tensor-core primitives (base sm_80+ PTX: valid in compute_103)
// ---------------------------------------------------------------------------
__device__ __forceinline__ uint32_t smem_u32(const void* p) {
    uint32_t a;
    asm("{ .reg .u64 t; cvta.to.shared.u64 t, %1; cvt.u32.u64 %0, t; }"
        : "=r"(a) : "l"(p));
    return a;
}
__device__ __forceinline__ void ldsm_x4(uint32_t* r, uint32_t a) {
    asm volatile("ldmatrix.sync.aligned.m8n8.x4.shared.b16 {%0,%1,%2,%3}, [%4];"
                 : "=r"(r[0]), "=r"(r[1]), "=r"(r[2]), "=r"(r[3]) : "r"(a));
}
__device__ __forceinline__ void ldsm_x4t(uint32_t* r, uint32_t a) {
    asm volatile("ldmatrix.sync.aligned.m8n8.x4.trans.shared.b16 {%0,%1,%2,%3}, [%4];"
                 : "=r"(r[0]), "=r"(r[1]), "=r"(r[2]), "=r"(r[3]) : "r"(a));
}
__device__ __forceinline__ void mma_bf16(float* c, const uint32_t* a, const uint32_t* b) {
    asm volatile("mma.sync.aligned.m16n8k16.row.col.f32.bf16.bf16.f32 "
                 "{%0,%1,%2,%3}, {%4,%5,%6,%7}, {%8,%9}, {%0,%1,%2,%3};"
                 : "+f"(c[0]), "+f"(c[1]), "+f"(c[2]), "+f"(c[3])
                 : "r"(a[0]), "r"(a[1]), "r"(a[2]), "r"(a[3]),
                   "r"(b[0]), "r"(b[1]));
}
#define CP_ASYNC16(s, g) \
    asm volatile("cp.async.cg.shared.global [%0], [%1], 16;" :: "r"(s), "l"(g))
#define CP_COMMIT() asm volatile("cp.async.commit_group;" ::: "memory")
#define CP_WAIT(N)  asm volatile("cp.async.wait_group %0;" :: "n"(N) : "memory")

__device__ __forceinline__ uint32_t packbf(float a, float b) {
    __nv_bfloat162 t = __floats2bfloat162_rn(a, b);
    return *(uint32_t*)&t;
}

// ---------------------------------------------------------------------------
// RoPE cos/sin table (double precision build)
// ---------------------------------------------------------------------------
__global__ void rope_table_kernel()
{
    int gid = blockIdx.x * blockDim.x + threadIdx.x;
    if (gid >= Tsz * 32) return;
    int t = gid >> 5, p = gid & 31;
    double alpha = pow(10000.0, -(double)p / 32.0);
    double ang = (double)t * alpha;
    g_cs[gid]            = (float)cos(ang);
    g_cs[Tsz * 32 + gid] = (float)sin(ang);
}

__global__ void set_biasp_kernel(const float* b0, const float* b1, const float* b2)
{
    g_biasp[0] = b0; g_biasp[1] = b1; g_biasp[2] = b2;
}

// ---------------------------------------------------------------------------
// fp32 -> (bf16 hi, bf16 lo) split conversion, float4-vectorized
// ---------------------------------------------------------------------------
__global__ void cvt_hilo_kernel(const float* __restrict__ src,
                                __nv_bfloat16* __restrict__ hi,
                                __nv_bfloat16* __restrict__ lo, int n4)
{
    int i = blockIdx.x * blockDim.x + threadIdx.x;
    if (i >= n4) return;
    float4 v = ((const float4*)src)[i];
    __nv_bfloat16 h0 = __float2bfloat16(v.x), h1 = __float2bfloat16(v.y);
    __nv_bfloat16 h2 = __float2bfloat16(v.z), h3 = __float2bfloat16(v.w);
    ((__nv_bfloat162*)hi)[2*i]   = __nv_bfloat162(h0, h1);
    ((__nv_bfloat162*)hi)[2*i+1] = __nv_bfloat162(h2, h3);
    ((__nv_bfloat162*)lo)[2*i]   = __floats2bfloat162_rn(
        v.x - __bfloat162float(h0), v.y - __bfloat162float(h1));
    ((__nv_bfloat162*)lo)[2*i+1] = __floats2bfloat162_rn(
        v.z - __bfloat162float(h2), v.w - __bfloat162float(h3));
}

// ---------------------------------------------------------------------------
// Shared split-bf16 GEMM mainloop (block 128x128, BK=32, 8 warps 4m x 2n).
// x4 ldmatrix for B (two nf per load).
// ---------------------------------------------------------------------------
#define GSTRIDE 80
#define GTILEB  (128 * GSTRIDE)
#define GSTAGEB (4 * GTILEB)
#define GSMEM   (2 * GSTAGEB)

__device__ __forceinline__ void gemm_mainloop(
    uint32_t sb, int tid, int lane, int mw, int nw,
    const char* s0, const char* s1, const char* s2, const char* s3,
    float acc[2][8][4])
{
    const int K = Csz;
    const char* srcs[4] = { s0, s1, s2, s3 };

    auto load_stage = [&](int s, int k0) {
        uint32_t sbase = sb + s * GSTAGEB;
#pragma unroll
        for (int t = 0; t < 4; ++t) {
#pragma unroll
            for (int c2 = 0; c2 < 2; ++c2) {
                int c = tid + c2 * 256;
                int row = c >> 2, sub = c & 3;
                const char* g = srcs[t] + (size_t)row * (K * 2) + k0 * 2 + sub * 16;
                CP_ASYNC16(sbase + t * GTILEB + row * GSTRIDE + sub * 16, g);
            }
        }
        CP_COMMIT();
    };

    load_stage(0, 0);

    for (int it = 0; it < 32; ++it) {
        const int s = it & 1;
        if (it + 1 < 32) { load_stage(s ^ 1, (it + 1) * 32); CP_WAIT(1); }
        else             { CP_WAIT(0); }
        __syncthreads();

        const uint32_t ah_b = sb + s * GSTAGEB;
        const uint32_t al_b = ah_b + GTILEB;
        const uint32_t bh_b = ah_b + 2 * GTILEB;
        const uint32_t bl_b = ah_b + 3 * GTILEB;

#pragma unroll
        for (int ks = 0; ks < 2; ++ks) {
            uint32_t a_hi[2][4], a_lo[2][4];
            const int acol = (ks * 16 + (lane >> 4) * 8) * 2;
#pragma unroll
            for (int mf = 0; mf < 2; ++mf) {
                int arow = mw * 32 + mf * 16 + (lane & 15);
                ldsm_x4(a_hi[mf], ah_b + arow * GSTRIDE + acol);
                ldsm_x4(a_lo[mf], al_b + arow * GSTRIDE + acol);
            }
            // B: x4 per nf-pair; r0,r1 -> nf=2j ; r2,r3 -> nf=2j+1
            const int brow = nw * 64 + (lane >> 4) * 8 + (lane & 7);
            const int bcol = (ks * 16 + ((lane >> 3) & 1) * 8) * 2;
#pragma unroll
            for (int j = 0; j < 4; ++j) {
                uint32_t bh4[4], bl4[4];
                ldsm_x4(bh4, bh_b + (brow + j * 16) * GSTRIDE + bcol);
                ldsm_x4(bl4, bl_b + (brow + j * 16) * GSTRIDE + bcol);
#pragma unroll
                for (int mf = 0; mf < 2; ++mf) {
                    mma_bf16(acc[mf][2*j],   a_hi[mf], bh4);
                    mma_bf16(acc[mf][2*j],   a_hi[mf], bl4);
                    mma_bf16(acc[mf][2*j],   a_lo[mf], bh4);
                    mma_bf16(acc[mf][2*j+1], a_hi[mf], bh4 + 2);
                    mma_bf16(acc[mf][2*j+1], a_hi[mf], bl4 + 2);
                    mma_bf16(acc[mf][2*j+1], a_lo[mf], bh4 + 2);
                }
            }
        }
        __syncthreads();
    }
}

// ---------------------------------------------------------------------------
// Merged QKV projection: grid (8, 64, 3); z selects {q,k,v}.
// bf16 hi/lo heads output [B,H,T,D], RoPE for z<2.
// ---------------------------------------------------------------------------
__global__ __launch_bounds__(256) void mma_gemm_qkv(
    const __nv_bfloat16* __restrict__ Ahi, const __nv_bfloat16* __restrict__ Alo)
{
    extern __shared__ char smem[];
    const uint32_t sb = smem_u32(smem);
    const int tid = threadIdx.x, lane = tid & 31, wid = tid >> 5;
    const int mw = wid >> 1, nw = wid & 1;
    const int m0 = blockIdx.y * 128, n0 = blockIdx.x * 128;
    const int z = blockIdx.z;

    const __nv_bfloat16 *Whi, *Wlo;
    __nv_bfloat16 *outhi, *outlo;
    if (z == 0)      { Whi = g_wqhi; Wlo = g_wqlo; outhi = g_qhi; outlo = g_qlo; }
    else if (z == 1) { Whi = g_wkhi; Wlo = g_wklo; outhi = g_khi; outlo = g_klo; }
    else             { Whi = g_wvhi; Wlo = g_wvlo; outhi = g_vhi; outlo = g_vlo; }
    const int rope = (z < 2);
    const float* bias = g_biasp[z];

    float acc[2][8][4];
#pragma unroll
    for (int mf = 0; mf < 2; ++mf)
#pragma unroll
        for (int nf = 0; nf < 8; ++nf)
#pragma unroll
            for (int e = 0; e < 4; ++e) acc[mf][nf][e] = 0.f;

    gemm_mainloop(sb, tid, lane, mw, nw,
                  (const char*)(Ahi + (size_t)m0 * Csz),
                  (const char*)(Alo + (size_t)m0 * Csz),
                  (const char*)(Whi + (size_t)n0 * Csz),
                  (const char*)(Wlo + (size_t)n0 * Csz), acc);

#pragma unroll
    for (int mf = 0; mf < 2; ++mf) {
#pragma unroll
        for (int half = 0; half < 2; ++half) {
            const int m = m0 + mw * 32 + mf * 16 + (lane >> 2) + half * 8;
            const int b = m >> 11, t = m & (Tsz - 1);
            const int h = (n0 + nw * 64) >> 6;
            const size_t base = (((size_t)b * Hsz + h) * Tsz + t) * Dsz;
            if (!rope) {
#pragma unroll
                for (int nf = 0; nf < 8; ++nf) {
                    int d = nf * 8 + (lane & 3) * 2;
                    int n = n0 + nw * 64 + d;
                    float v0 = acc[mf][nf][half * 2 + 0] + __ldg(&bias[n]);
                    float v1 = acc[mf][nf][half * 2 + 1] + __ldg(&bias[n + 1]);
                    __nv_bfloat16 h0 = __float2bfloat16(v0), h1 = __float2bfloat16(v1);
                    *(__nv_bfloat162*)(outhi + base + d) = __nv_bfloat162(h0, h1);
                    *(__nv_bfloat162*)(outlo + base + d) =
                        __floats2bfloat162_rn(v0 - __bfloat162float(h0),
                                              v1 - __bfloat162float(h1));
                }
            } else {
#pragma unroll
                for (int nf = 0; nf < 4; ++nf) {
#pragma unroll
                    for (int e = 0; e < 2; ++e) {
                        int d = nf * 8 + (lane & 3) * 2 + e;
                        int n = n0 + nw * 64 + d;
                        float xr = acc[mf][nf][half * 2 + e]     + __ldg(&bias[n]);
                        float xi = acc[mf][nf + 4][half * 2 + e] + __ldg(&bias[n + 32]);
                        float cth = __ldg(&g_cs[t * 32 + d]);
                        float sth = __ldg(&g_cs[Tsz * 32 + t * 32 + d]);
                        float r0 = xr * cth - xi * sth;
                        float r1 = xr * sth + xi * cth;
                        __nv_bfloat16 h0 = __float2bfloat16(r0);
                        __nv_bfloat16 h1 = __float2bfloat16(r1);
                        outhi[base + d]      = h0;
                        outhi[base + d + 32] = h1;
                        outlo[base + d]      = __float2bfloat16(r0 - __bfloat162float(h0));
                        outlo[base + d + 32] = __float2bfloat16(r1 - __bfloat162float(h1));
                    }
                }
            }
        }
    }
}

// ---------------------------------------------------------------------------
// Output projection: fp32 out[m*N+n] = Yhi/lo @ Wp^T + bias
// ---------------------------------------------------------------------------
__global__ __launch_bounds__(256) void mma_gemm_proj(
    const __nv_bfloat16* __restrict__ Ahi, const __nv_bfloat16* __restrict__ Alo,
    const __nv_bfloat16* __restrict__ Whi, const __nv_bfloat16* __restrict__ Wlo,
    const float* __restrict__ bias, float* __restrict__ outf)
{
    extern __shared__ char smem[];
    const uint32_t sb = smem_u32(smem);
    const int tid = threadIdx.x, lane = tid & 31, wid = tid >> 5;
    const int mw = wid >> 1, nw = wid & 1;
    const int m0 = blockIdx.y * 128, n0 = blockIdx.x * 128;

    float acc[2][8][4];
#pragma unroll
    for (int mf = 0; mf < 2; ++mf)
#pragma unroll
        for (int nf = 0; nf < 8; ++nf)
#pragma unroll
            for (int e = 0; e < 4; ++e) acc[mf][nf][e] = 0.f;

    gemm_mainloop(sb, tid, lane, mw, nw,
                  (const char*)(Ahi + (size_t)m0 * Csz),
                  (const char*)(Alo + (size_t)m0 * Csz),
                  (const char*)(Whi + (size_t)n0 * Csz),
                  (const char*)(Wlo + (size_t)n0 * Csz), acc);

#pragma unroll
    for (int mf = 0; mf < 2; ++mf)
#pragma unroll
        for (int half = 0; half < 2; ++half) {
            const int m = m0 + mw * 32 + mf * 16 + (lane >> 2) + half * 8;
#pragma unroll
            for (int nf = 0; nf < 8; ++nf) {
                int n = n0 + nw * 64 + nf * 8 + (lane & 3) * 2;
                outf[(size_t)m * Csz + n]     = acc[mf][nf][half * 2 + 0] + __ldg(&bias[n]);
                outf[(size_t)m * Csz + n + 1] = acc[mf][nf][half * 2 + 1] + __ldg(&bias[n + 1]);
            }
        }
}

// ---------------------------------------------------------------------------
// Causal flash attention, split-bf16 mma.sync.
// Block: 256 threads (8 warps), 128 q-rows; warp owns 16 rows x 64 cols.
// K/V 64-row tiles (hi/lo) double-buffered via cp.async; x4 ldmatrix.
// ---------------------------------------------------------------------------
#define ASTRIDE 144
#define ATILE   (64 * ASTRIDE)          // 9216
#define ASTAGE  (4 * ATILE)             // 36864
#define ASMEM   (2 * ASTAGE)            // 73728

__global__ __launch_bounds__(256) void attn_mma(
    const __nv_bfloat16* __restrict__ Qhi, const __nv_bfloat16* __restrict__ Qlo,
    const __nv_bfloat16* __restrict__ Khi, const __nv_bfloat16* __restrict__ Klo,
    const __nv_bfloat16* __restrict__ Vhi, const __nv_bfloat16* __restrict__ Vlo,
    __nv_bfloat16* __restrict__ Yhi, __nv_bfloat16* __restrict__ Ylo)
{
    extern __shared__ char smem[];
    const uint32_t sb = smem_u32(smem);
    const int tid = threadIdx.x, lane = tid & 31, w = tid >> 5;
    const int bh = blockIdx.y, qb = blockIdx.x;      // qb: 128-row q tile
    const int rbase = qb * 128 + w * 16;             // warp's first q row (global)

    // ---- stage Q hi/lo (128 rows) into stage0; extract A fragments ----
    {
        const char* s0 = (const char*)(Qhi + ((size_t)bh * Tsz + qb * 128) * Dsz);
        const char* s1 = (const char*)(Qlo + ((size_t)bh * Tsz + qb * 128) * Dsz);
#pragma unroll
        for (int i = 0; i < 4; ++i) {
            int c = tid + i * 256, row = c >> 3, sub = c & 7;   // 1024 chunks/tile
            CP_ASYNC16(sb +         row * ASTRIDE + sub * 16, s0 + row * 128 + sub * 16);
            CP_ASYNC16(sb + 18432 + row * ASTRIDE + sub * 16, s1 + row * 128 + sub * 16);
        }
        CP_COMMIT(); CP_WAIT(0);
        __syncthreads();
    }
    uint32_t qh[4][4], ql[4][4];
    {
        const int arow = w * 16 + (lane & 15);
        const int acoff = (lane >> 4) * 8;
#pragma unroll
        for (int kt = 0; kt < 4; ++kt) {
            ldsm_x4(qh[kt], sb +         arow * ASTRIDE + (acoff + kt * 16) * 2);
            ldsm_x4(ql[kt], sb + 18432 + arow * ASTRIDE + (acoff + kt * 16) * 2);
        }
    }
    __syncthreads();

    const char* kh_p = (const char*)(Khi + (size_t)bh * Tsz * Dsz);
    const char* kl_p = (const char*)(Klo + (size_t)bh * Tsz * Dsz);
    const char* vh_p = (const char*)(Vhi + (size_t)bh * Tsz * Dsz);
    const char* vl_p = (const char*)(Vlo + (size_t)bh * Tsz * Dsz);

    auto load_kv = [&](int st, int kb) {
        uint32_t sbase = sb + st * ASTAGE;
        const char* srcs[4] = { kh_p + (size_t)kb * 64 * 128, kl_p + (size_t)kb * 64 * 128,
                                vh_p + (size_t)kb * 64 * 128, vl_p + (size_t)kb * 64 * 128 };
#pragma unroll
        for (int t = 0; t < 4; ++t)
#pragma unroll
            for (int i = 0; i < 2; ++i) {                       // 512 chunks/tile
                int c = tid + i * 256, row = c >> 3, sub = c & 7;
                CP_ASYNC16(sbase + t * ATILE + row * ASTRIDE + sub * 16,
                           srcs[t] + row * 128 + sub * 16);
            }
        CP_COMMIT();
    };

    float o[8][4];
    float mrow[2] = { -INFINITY, -INFINITY }, lrow[2] = { 0.f, 0.f };
#pragma unroll
    for (int nf = 0; nf < 8; ++nf)
#pragma unroll
        for (int e = 0; e < 4; ++e) o[nf][e] = 0.f;

    const int kbmax = 2 * qb + 1;
    load_kv(0, 0);

    for (int kb = 0; kb <= kbmax; ++kb) {
        const int st = kb & 1;
        if (kb < kbmax) { load_kv(st ^ 1, kb + 1); CP_WAIT(1); }
        else            { CP_WAIT(0); }
        __syncthreads();

        const bool active = (kb * 64 <= rbase + 15);
        if (active) {
            const uint32_t khb = sb + st * ASTAGE;
            const uint32_t klb = khb + ATILE;
            const uint32_t vhb = khb + 2 * ATILE;
            const uint32_t vlb = khb + 3 * ATILE;

            // ---- S = Q @ K^T (split), x4 K-loads (two nf per load) ----
            float s[8][4];
#pragma unroll
            for (int nf = 0; nf < 8; ++nf)
#pragma unroll
                for (int e = 0; e < 4; ++e) s[nf][e] = 0.f;

            const int krow = (lane >> 4) * 8 + (lane & 7);
#pragma unroll
            for (int kt = 0; kt < 4; ++kt) {
                const int kcol = (kt * 16 + ((lane >> 3) & 1) * 8) * 2;
#pragma unroll
                for (int j = 0; j < 4; ++j) {
                    uint32_t kh4[4], kl4[4];
                    ldsm_x4(kh4, khb + (j * 16 + krow) * ASTRIDE + kcol);
                    ldsm_x4(kl4, klb + (j * 16 + krow) * ASTRIDE + kcol);
                    mma_bf16(s[2*j],   qh[kt], kh4);
                    mma_bf16(s[2*j],   qh[kt], kl4);
                    mma_bf16(s[2*j],   ql[kt], kh4);
                    mma_bf16(s[2*j+1], qh[kt], kh4 + 2);
                    mma_bf16(s[2*j+1], qh[kt], kl4 + 2);
                    mma_bf16(s[2*j+1], ql[kt], kh4 + 2);
                }
            }

            // scale + causal mask (only near diagonal)
#pragma unroll
            for (int nf = 0; nf < 8; ++nf)
#pragma unroll
                for (int e = 0; e < 4; ++e) s[nf][e] *= 0.125f;
            if (kb * 64 + 63 > rbase) {
#pragma unroll
                for (int nf = 0; nf < 8; ++nf)
#pragma unroll
                    for (int e = 0; e < 4; ++e) {
                        int col = kb * 64 + nf * 8 + (lane & 3) * 2 + (e & 1);
                        int row = rbase + (lane >> 2) + (e >> 1) * 8;
                        if (col > row) s[nf][e] = -INFINITY;
                    }
            }

            // ---- online softmax (row = 4-lane group) ----
#pragma unroll
            for (int half = 0; half < 2; ++half) {
                float mt = -INFINITY;
#pragma unroll
                for (int nf = 0; nf < 8; ++nf) {
                    mt = fmaxf(mt, s[nf][half * 2 + 0]);
                    mt = fmaxf(mt, s[nf][half * 2 + 1]);
                }
                mt = fmaxf(mt, __shfl_xor_sync(0xffffffffu, mt, 1));
                mt = fmaxf(mt, __shfl_xor_sync(0xffffffffu, mt, 2));
                float mnew = fmaxf(mrow[half], mt);
                float corr = __expf(mrow[half] - mnew);
                float lt = 0.f;
#pragma unroll
                for (int nf = 0; nf < 8; ++nf) {
                    float p0 = __expf(s[nf][half * 2 + 0] - mnew);
                    float p1 = __expf(s[nf][half * 2 + 1] - mnew);
                    s[nf][half * 2 + 0] = p0; s[nf][half * 2 + 1] = p1;
                    lt += p0 + p1;
                }
                lt += __shfl_xor_sync(0xffffffffu, lt, 1);
                lt += __shfl_xor_sync(0xffffffffu, lt, 2);
                lrow[half] = lrow[half] * corr + lt;
                mrow[half] = mnew;
#pragma unroll
                for (int nf = 0; nf < 8; ++nf) {
                    o[nf][half * 2 + 0] *= corr;
                    o[nf][half * 2 + 1] *= corr;
                }
            }

            // ---- O += P @ V (split); P acc-frags -> A-frags; x4.trans V ----
#pragma unroll
            for (int kt = 0; kt < 4; ++kt) {
                uint32_t pa_h[4], pa_l[4];
#pragma unroll
                for (int g = 0; g < 2; ++g) {
                    const float* f = s[2 * kt + g];
                    __nv_bfloat16 h0 = __float2bfloat16(f[0]), h1 = __float2bfloat16(f[1]);
                    __nv_bfloat16 h2 = __float2bfloat16(f[2]), h3 = __float2bfloat16(f[3]);
                    pa_h[2 * g + 0] = packbf(f[0], f[1]);
                    pa_h[2 * g + 1] = packbf(f[2], f[3]);
                    pa_l[2 * g + 0] = packbf(f[0] - __bfloat162float(h0),
                                             f[1] - __bfloat162float(h1));
                    pa_l[2 * g + 1] = packbf(f[2] - __bfloat162float(h2),
                                             f[3] - __bfloat162float(h3));
                }
                const int vrow = (kt * 16 + (lane & 15)) * ASTRIDE;
                const int vco  = (lane >> 4) * 16;
#pragma unroll
                for (int j = 0; j < 4; ++j) {
                    uint32_t vh4[4], vl4[4];
                    ldsm_x4t(vh4, vhb + vrow + j * 32 + vco);
                    ldsm_x4t(vl4, vlb + vrow + j * 32 + vco);
                    mma_bf16(o[2*j],   pa_h, vh4);
                    mma_bf16(o[2*j],   pa_h, vl4);
                    mma_bf16(o[2*j],   pa_l, vh4);
                    mma_bf16(o[2*j+1], pa_h, vh4 + 2);
                    mma_bf16(o[2*j+1], pa_h, vl4 + 2);
                    mma_bf16(o[2*j+1], pa_l, vh4 + 2);
                }
            }
        }
        __syncthreads();
    }

    // ---- epilogue: normalize, split, write [B,T,C] bf16 hi/lo ----
    const int b = bh >> 4, h = bh & 15;
#pragma unroll
    for (int half = 0; half < 2; ++half) {
        const int t = rbase + (lane >> 2) + half * 8;
        const float inv = 1.f / lrow[half];
        const size_t base = ((size_t)b * Tsz + t) * Csz + h * 64;
#pragma unroll
        for (int nf = 0; nf < 8; ++nf) {
            int d = nf * 8 + (lane & 3) * 2;
            float v0 = o[nf][half * 2 + 0] * inv;
            float v1 = o[nf][half * 2 + 1] * inv;
            __nv_bfloat16 h0 = __float2bfloat16(v0), h1 = __float2bfloat16(v1);
            *(__nv_bfloat162*)(Yhi + base + d) = __nv_bfloat162(h0, h1);
            *(__nv_bfloat162*)(Ylo + base + d) =
                __floats2bfloat162_rn(v0 - __bfloat162float(h0),
                                      v1 - __bfloat162float(h1));
        }
    }
}

// ---------------------------------------------------------------------------
// Launch
// ---------------------------------------------------------------------------
extern "C" void kernel_launch(void* const* d_in, const int* in_sizes, int n_in,
                              void* d_out, int out_size)
{
    const float* x  = (const float*)d_in[0];
    const float* wq = (const float*)d_in[1];
    const float* bq = (const float*)d_in[2];
    const float* wk = (const float*)d_in[3];
    const float* bk = (const float*)d_in[4];
    const float* wv = (const float*)d_in[5];
    const float* bv = (const float*)d_in[6];
    const float* wp = (const float*)d_in[7];
    const float* bp = (const float*)d_in[8];
    float* out = (float*)d_out;

    __nv_bfloat16 *xhi, *xlo, *yhi, *ylo;
    __nv_bfloat16 *qhi, *qlo, *khi, *klo, *vhi, *vlo;
    __nv_bfloat16 *wqhi, *wqlo, *wkhi, *wklo, *wvhi, *wvlo, *wphi, *wplo;
    cudaGetSymbolAddress((void**)&xhi, g_xhi);   cudaGetSymbolAddress((void**)&xlo, g_xlo);
    cudaGetSymbolAddress((void**)&yhi, g_yhi);   cudaGetSymbolAddress((void**)&ylo, g_ylo);
    cudaGetSymbolAddress((void**)&qhi, g_qhi);   cudaGetSymbolAddress((void**)&qlo, g_qlo);
    cudaGetSymbolAddress((void**)&khi, g_khi);   cudaGetSymbolAddress((void**)&klo, g_klo);
    cudaGetSymbolAddress((void**)&vhi, g_vhi);   cudaGetSymbolAddress((void**)&vlo, g_vlo);
    cudaGetSymbolAddress((void**)&wqhi, g_wqhi); cudaGetSymbolAddress((void**)&wqlo, g_wqlo);
    cudaGetSymbolAddress((void**)&wkhi, g_wkhi); cudaGetSymbolAddress((void**)&wklo, g_wklo);
    cudaGetSymbolAddress((void**)&wvhi, g_wvhi); cudaGetSymbolAddress((void**)&wvlo, g_wvlo);
    cudaGetSymbolAddress((void**)&wphi, g_wphi); cudaGetSymbolAddress((void**)&wplo, g_wplo);

    rope_table_kernel<<<(Tsz * 32 + 255) / 256, 256>>>();
    set_biasp_kernel<<<1, 1>>>(bq, bk, bv);

    const int nx4 = Msz * Csz / 4, nw4 = Csz * Csz / 4;
    cvt_hilo_kernel<<<(nx4 + 255) / 256, 256>>>(x,  xhi,  xlo,  nx4);
    cvt_hilo_kernel<<<(nw4 + 255) / 256, 256>>>(wq, wqhi, wqlo, nw4);
    cvt_hilo_kernel<<<(nw4 + 255) / 256, 256>>>(wk, wkhi, wklo, nw4);
    cvt_hilo_kernel<<<(nw4 + 255) / 256, 256>>>(wv, wvhi, wvlo, nw4);
    cvt_hilo_kernel<<<(nw4 + 255) / 256, 256>>>(wp, wphi, wplo, nw4);

    cudaFuncSetAttribute(mma_gemm_qkv,  cudaFuncAttributeMaxDynamicSharedMemorySize, GSMEM);
    cudaFuncSetAttribute(mma_gemm_proj, cudaFuncAttributeMaxDynamicSharedMemorySize, GSMEM);
    cudaFuncSetAttribute(attn_mma,      cudaFuncAttributeMaxDynamicSharedMemorySize, ASMEM);

    mma_gemm_qkv<<<dim3(Csz / 128, Msz / 128, 3), 256, GSMEM>>>(xhi, xlo);

    attn_mma<<<dim3(Tsz / 128, BH), 256, ASMEM>>>(qhi, qlo, khi, klo, vhi, vlo, yhi, ylo);

    mma_gemm_proj<<<dim3(Csz / 128, Msz / 128), 256, GSMEM>>>(yhi, ylo, wphi, wplo, bp, out);
}